// round 3
// baseline (speedup 1.0000x reference)
#include <cuda_runtime.h>
#include <math.h>

#define BB 8
#define CC 128
#define NPIX (512*512)          // pixels per batch image
#define WORDS (NPIX/32)         // 8192 bitmask words per batch
#define SPLIT 16                // blocks per (b,c) plane in sum pass
#define CHUNK (NPIX/SPLIT)      // 16384 elements per block
#define EPSV 1e-12f

// ---- scratch (no allocations allowed) ----
__device__ float        g_sumC[BB*CC];
__device__ float        g_sumN[BB*CC];
__device__ int          g_cntC[BB];
__device__ int          g_cntN[BB];
__device__ float        g_dvec[BB*CC];
__device__ float        g_valid[BB];
__device__ unsigned int g_maskC[BB*WORDS];   // bit=1 where gt==1
__device__ unsigned int g_maskN[BB*WORDS];   // bit=1 where gt==0

// ---------------- zero accumulators ----------------
__global__ void k_zero() {
    int i = blockIdx.x * blockDim.x + threadIdx.x;
    if (i < BB*CC) { g_sumC[i] = 0.f; g_sumN[i] = 0.f; }
    if (i < BB)    { g_cntC[i] = 0;   g_cntN[i] = 0;   }
}

// ---------------- pack gt into bitmasks + class counts ----------------
// grid: (WORDS/256, BB), 256 threads. One mask word (32 pixels) per thread.
__global__ void k_pack(const int* __restrict__ gt) {
    int b = blockIdx.y;
    int w = blockIdx.x * 256 + threadIdx.x;          // word index within batch
    const int4* g4 = (const int4*)(gt + (size_t)b * NPIX) + (size_t)w * 8;
    unsigned int mc = 0u, mn = 0u;
    #pragma unroll
    for (int i = 0; i < 8; i++) {
        int4 g = g4[i];
        mc |= ((g.x==1) ? 1u : 0u) << (i*4 + 0);
        mc |= ((g.y==1) ? 1u : 0u) << (i*4 + 1);
        mc |= ((g.z==1) ? 1u : 0u) << (i*4 + 2);
        mc |= ((g.w==1) ? 1u : 0u) << (i*4 + 3);
        mn |= ((g.x==0) ? 1u : 0u) << (i*4 + 0);
        mn |= ((g.y==0) ? 1u : 0u) << (i*4 + 1);
        mn |= ((g.z==0) ? 1u : 0u) << (i*4 + 2);
        mn |= ((g.w==0) ? 1u : 0u) << (i*4 + 3);
    }
    g_maskC[b*WORDS + w] = mc;
    g_maskN[b*WORDS + w] = mn;

    int cc = __popc(mc), cn = __popc(mn);
    #pragma unroll
    for (int o = 16; o; o >>= 1) {
        cc += __shfl_down_sync(0xffffffffu, cc, o);
        cn += __shfl_down_sync(0xffffffffu, cn, o);
    }
    __shared__ int sc[8], sn[8];
    int wp = threadIdx.x >> 5;
    if ((threadIdx.x & 31) == 0) { sc[wp] = cc; sn[wp] = cn; }
    __syncthreads();
    if (threadIdx.x == 0) {
        int tc = 0, tn = 0;
        for (int i = 0; i < 8; i++) { tc += sc[i]; tn += sn[i]; }
        atomicAdd(&g_cntC[b], tc);
        atomicAdd(&g_cntN[b], tn);
    }
}

// ---------------- masked channel sums (bitmask; gt traffic ~0) ----------------
// grid: (SPLIT, CC, BB), 256 threads
__global__ void k_sums(const float* __restrict__ fm) {
    int chunk = blockIdx.x, c = blockIdx.y, b = blockIdx.z;
    const float4* f4 = (const float4*)(fm + ((size_t)(b*CC + c)) * NPIX + (size_t)chunk * CHUNK);
    const unsigned int* mC = g_maskC + b*WORDS + chunk*(CHUNK/32);
    const unsigned int* mN = g_maskN + b*WORDS + chunk*(CHUNK/32);
    float sc = 0.f, sn = 0.f;
    const int nvec = CHUNK / 4;  // 4096 float4s
    #pragma unroll 8
    for (int j = threadIdx.x; j < nvec; j += 256) {
        float4 v = f4[j];
        unsigned int wc = mC[j >> 3];
        unsigned int wn = mN[j >> 3];
        int sh = (j & 7) * 4;
        sc += ((wc >> (sh+0)) & 1u ? v.x : 0.f) + ((wc >> (sh+1)) & 1u ? v.y : 0.f)
            + ((wc >> (sh+2)) & 1u ? v.z : 0.f) + ((wc >> (sh+3)) & 1u ? v.w : 0.f);
        sn += ((wn >> (sh+0)) & 1u ? v.x : 0.f) + ((wn >> (sh+1)) & 1u ? v.y : 0.f)
            + ((wn >> (sh+2)) & 1u ? v.z : 0.f) + ((wn >> (sh+3)) & 1u ? v.w : 0.f);
    }
    #pragma unroll
    for (int o = 16; o; o >>= 1) {
        sc += __shfl_down_sync(0xffffffffu, sc, o);
        sn += __shfl_down_sync(0xffffffffu, sn, o);
    }
    __shared__ float shc[8], shn[8];
    int w = threadIdx.x >> 5;
    if ((threadIdx.x & 31) == 0) { shc[w] = sc; shn[w] = sn; }
    __syncthreads();
    if (threadIdx.x == 0) {
        float tc = 0.f, tn = 0.f;
        for (int i = 0; i < 8; i++) { tc += shc[i]; tn += shn[i]; }
        atomicAdd(&g_sumC[b*CC + c], tc);
        atomicAdd(&g_sumN[b*CC + c], tn);
    }
}

// ---------------- prototype normalize + difference vector ----------------
// grid: BB blocks, CC threads
__global__ void k_proto() {
    int b = blockIdx.x, c = threadIdx.x;
    float nc = (float)g_cntC[b];
    float nn = (float)g_cntN[b];
    float pc = g_sumC[b*CC + c] / fmaxf(nc, 1.f);
    float pn = g_sumN[b*CC + c] / fmaxf(nn, 1.f);
    float s1 = pc*pc, s2 = pn*pn;
    #pragma unroll
    for (int o = 16; o; o >>= 1) {
        s1 += __shfl_down_sync(0xffffffffu, s1, o);
        s2 += __shfl_down_sync(0xffffffffu, s2, o);
    }
    __shared__ float r1[4], r2[4];
    int w = c >> 5;
    if ((c & 31) == 0) { r1[w] = s1; r2[w] = s2; }
    __syncthreads();
    float t1 = r1[0] + r1[1] + r1[2] + r1[3];
    float t2 = r2[0] + r2[1] + r2[2] + r2[3];
    float npc = fmaxf(sqrtf(t1), EPSV);
    float npn = fmaxf(sqrtf(t2), EPSV);
    g_dvec[b*CC + c] = pc / npc - pn / npn;
    if (c == 0) g_valid[b] = (nc > 0.f && nn > 0.f) ? 1.f : 0.f;
}

// ---------------- per-pixel similarity + exp ----------------
// grid: (NPIX/1024, BB), 256 threads, each thread 4 pixels (float4)
__global__ void k_out(const float* __restrict__ fm, float* __restrict__ out) {
    int b = blockIdx.y;
    __shared__ float sd[CC];
    __shared__ float sval;
    if (threadIdx.x < CC) sd[threadIdx.x] = g_dvec[b*CC + threadIdx.x];
    if (threadIdx.x == 0) sval = g_valid[b];
    __syncthreads();

    int base = blockIdx.x * 256 + threadIdx.x;          // float4 index within batch plane
    const float4* f4 = (const float4*)(fm + (size_t)b * CC * NPIX);

    float4 s = {0.f,0.f,0.f,0.f};
    float4 q = {0.f,0.f,0.f,0.f};
    #pragma unroll 8
    for (int c = 0; c < CC; c++) {
        float4 v = f4[(size_t)c * (NPIX/4) + base];
        float dc = sd[c];
        s.x += v.x * dc;  q.x += v.x * v.x;
        s.y += v.y * dc;  q.y += v.y * v.y;
        s.z += v.z * dc;  q.z += v.z * v.z;
        s.w += v.w * dc;  q.w += v.w * v.w;
    }
    unsigned int wc = g_maskC[b*WORDS + (base >> 3)];
    int sh = (base & 7) * 4;
    float val = sval;
    float4 o;
    o.x = val * __expf(((wc >> (sh+0)) & 1u ? 1.f : -1.f) * s.x / fmaxf(sqrtf(q.x), EPSV));
    o.y = val * __expf(((wc >> (sh+1)) & 1u ? 1.f : -1.f) * s.y / fmaxf(sqrtf(q.y), EPSV));
    o.z = val * __expf(((wc >> (sh+2)) & 1u ? 1.f : -1.f) * s.z / fmaxf(sqrtf(q.z), EPSV));
    o.w = val * __expf(((wc >> (sh+3)) & 1u ? 1.f : -1.f) * s.w / fmaxf(sqrtf(q.w), EPSV));
    ((float4*)(out + (size_t)b * NPIX))[base] = o;
}

extern "C" void kernel_launch(void* const* d_in, const int* in_sizes, int n_in,
                              void* d_out, int out_size) {
    const float* fm = (const float*)d_in[0];
    const int*   gt = (const int*)d_in[1];
    float* out = (float*)d_out;

    k_zero<<<(BB*CC + 255)/256, 256>>>();
    {
        dim3 grid(WORDS/256, BB);
        k_pack<<<grid, 256>>>(gt);
    }
    {
        dim3 grid(SPLIT, CC, BB);
        k_sums<<<grid, 256>>>(fm);
    }
    k_proto<<<BB, CC>>>();
    {
        dim3 grid(NPIX/1024, BB);
        k_out<<<grid, 256>>>(fm, out);
    }
}